// round 15
// baseline (speedup 1.0000x reference)
#include <cuda_runtime.h>
#include <cuda_fp16.h>
#include <math.h>
#include <stdint.h>

typedef unsigned long long ull;

// ---------------- device scratch (no allocs allowed) ----------------
__device__ __align__(16) __half d_Mh[4096ull * 4096ull];  // |FFT| magnitudes, fp16, 32MB
__device__ float d_G[64 * 4096];                          // G'[i,h,w], 1MB
__device__ float d_sp4[16 * 64 * 4096];                   // conv partials (16 groups), 16MB
__device__ float d_sp[64 * 4096];                         // reduced conv, 1MB

// ---------------- packed f32x2 helpers ----------------
__device__ __forceinline__ ull PK(float x, float y) {
    ull r; asm("mov.b64 %0,{%1,%2};" : "=l"(r) : "f"(x), "f"(y)); return r;
}
__device__ __forceinline__ float2 UPK(ull v) {
    float2 r; asm("mov.b64 {%0,%1},%2;" : "=f"(r.x), "=f"(r.y) : "l"(v)); return r;
}
__device__ __forceinline__ ull PADD(ull a, ull b) {
    ull d; asm("add.rn.f32x2 %0,%1,%2;" : "=l"(d) : "l"(a), "l"(b)); return d;
}
__device__ __forceinline__ ull PFMA(ull a, ull b, ull c) {
    ull d; asm("fma.rn.f32x2 %0,%1,%2,%3;" : "=l"(d) : "l"(a), "l"(b), "l"(c)); return d;
}
__device__ __forceinline__ ull PSUB(ull a, ull b) {
    return PFMA(b, PK(-1.f, -1.f), a);
}

// ---------------- MMA helpers ----------------
__device__ __forceinline__ void ldsm_x4(uint32_t (&r)[4], uint32_t addr) {
    asm volatile("ldmatrix.sync.aligned.m8n8.x4.shared.b16 {%0,%1,%2,%3}, [%4];"
                 : "=r"(r[0]), "=r"(r[1]), "=r"(r[2]), "=r"(r[3]) : "r"(addr));
}
__device__ __forceinline__ void ldsm_x2_trans(uint32_t (&r)[2], uint32_t addr) {
    asm volatile("ldmatrix.sync.aligned.m8n8.x2.trans.shared.b16 {%0,%1}, [%2];"
                 : "=r"(r[0]), "=r"(r[1]) : "r"(addr));
}
__device__ __forceinline__ void mma16816(float (&d)[4], const uint32_t (&a)[4], const uint32_t (&b)[2]) {
    asm volatile(
        "mma.sync.aligned.m16n8k16.row.col.f32.f16.f16.f32 "
        "{%0,%1,%2,%3},{%4,%5,%6,%7},{%8,%9},{%0,%1,%2,%3};"
        : "+f"(d[0]), "+f"(d[1]), "+f"(d[2]), "+f"(d[3])
        : "r"(a[0]), "r"(a[1]), "r"(a[2]), "r"(a[3]), "r"(b[0]), "r"(b[1]));
}

// ---------------- FFT smem layout ----------------
#define FFT_SM_F2 (64 * 72)
__device__ __forceinline__ int fft_phys(int r, int c) { return r * 72 + (c ^ (r & 7)); }

// 8-point DIF FFT on packed complex (re,im) in f32x2 registers. SGN=-1 fwd, +1 inv.
template <int SGN>
__device__ __forceinline__ void fft8p(ull v[8]) {
    const float S = (float)SGN;
    const float C = 0.70710678118654752440f;
    ull t0 = PADD(v[0], v[4]), t4 = PSUB(v[0], v[4]);
    ull t1 = PADD(v[1], v[5]), t5 = PSUB(v[1], v[5]);
    ull t2 = PADD(v[2], v[6]), t6 = PSUB(v[2], v[6]);
    ull t3 = PADD(v[3], v[7]), t7 = PSUB(v[3], v[7]);
    float2 f5 = UPK(t5), f6 = UPK(t6), f7 = UPK(t7);
    t5 = PK(C * (f5.x - S * f5.y), C * (S * f5.x + f5.y));
    t6 = PK(-S * f6.y, S * f6.x);
    t7 = PK(C * (-f7.x - S * f7.y), C * (S * f7.x - f7.y));
    ull u0 = PADD(t0, t2), u2 = PSUB(t0, t2);
    ull u1 = PADD(t1, t3);
    float2 d13 = UPK(PSUB(t1, t3));
    ull u3 = PK(-S * d13.y, S * d13.x);
    ull u4 = PADD(t4, t6), u6 = PSUB(t4, t6);
    ull u5 = PADD(t5, t7);
    float2 d57 = UPK(PSUB(t5, t7));
    ull u7 = PK(-S * d57.y, S * d57.x);
    v[0] = PADD(u0, u1); v[4] = PSUB(u0, u1);
    v[2] = PADD(u2, u3); v[6] = PSUB(u2, u3);
    v[1] = PADD(u4, u5); v[5] = PSUB(u4, u5);
    v[3] = PADD(u6, u7); v[7] = PSUB(u6, u7);
}

__device__ __forceinline__ ull tw_mul(ull z, float2 w) {
    float2 f = UPK(z);
    return PK(f.x * w.x - f.y * w.y, f.x * w.y + f.y * w.x);
}

// Row pass with input already in registers (v[n1] = z[g][8*n1+t]).
template <int SGN>
__device__ __forceinline__ void row_pass_reg(ull v[8], float2* smf, const float2* s_tw, int tid) {
    ull* sm = (ull*)smf;
    const int g = tid >> 3, t = tid & 7;
    fft8p<SGN>(v);
#pragma unroll
    for (int k1 = 1; k1 < 8; k1++) {
        float2 w = s_tw[(t * k1) & 63];
        if (SGN == 1) w.y = -w.y;
        v[k1] = tw_mul(v[k1], w);
    }
    __syncwarp();
#pragma unroll
    for (int k1 = 0; k1 < 8; k1++) sm[fft_phys(g, 8 * k1 + (t ^ k1))] = v[k1];
    __syncwarp();
#pragma unroll
    for (int n2 = 0; n2 < 8; n2++) v[n2] = sm[fft_phys(g, 8 * t + (n2 ^ t))];
    fft8p<SGN>(v);
    __syncwarp();
#pragma unroll
    for (int k2 = 0; k2 < 8; k2++) sm[fft_phys(g, t + 8 * k2)] = v[k2];
}

// One pass (rows or cols) of a 64x64 2D FFT in shared memory (LDS-sourced).
template <int SGN, bool ROWS>
__device__ __forceinline__ void fft_pass(float2* smf, const float2* s_tw, int tid) {
    ull* sm = (ull*)smf;
    const int g = tid >> 3;
    const int t = tid & 7;
#define LIDX(m) (ROWS ? fft_phys(g, (m)) : fft_phys((m), g))
    ull v[8];
#pragma unroll
    for (int n1 = 0; n1 < 8; n1++) v[n1] = sm[LIDX(8 * n1 + t)];
    fft8p<SGN>(v);
#pragma unroll
    for (int k1 = 1; k1 < 8; k1++) {
        float2 w = s_tw[(t * k1) & 63];
        if (SGN == 1) w.y = -w.y;
        v[k1] = tw_mul(v[k1], w);
    }
    __syncwarp();
#pragma unroll
    for (int k1 = 0; k1 < 8; k1++) sm[LIDX(8 * k1 + (t ^ k1))] = v[k1];
    __syncwarp();
#pragma unroll
    for (int n2 = 0; n2 < 8; n2++) v[n2] = sm[LIDX(8 * t + (n2 ^ t))];
    fft8p<SGN>(v);
    __syncwarp();
#pragma unroll
    for (int k2 = 0; k2 < 8; k2++) sm[LIDX(t + 8 * k2)] = v[k2];
#undef LIDX
}

// needed(B): does G[B] (built from batch-B magnitudes) feed any surviving plane?
__device__ __forceinline__ bool batch_needed(const float* __restrict__ fbs, int B,
                                             int tid, int* s_flag) {
    if (tid == 0) *s_flag = 0;
    __syncthreads();
    if (tid < 64) {
        int si = (int)floorf((fbs[tid * 2 + 0] + 1.f) * 0.5f * 64.f);
        int ei = (int)floorf((fbs[tid * 2 + 1] + 1.f) * 0.5f * 64.f);
        int iB = (B + 32) & 63;
        if (iB >= si && iB < ei) *s_flag = 1;
    }
    __syncthreads();
    return *s_flag != 0;
}

// ---------------- kernel 1: fused [3x3 conv partials (4ch/block)] + [two-for-one fwd FFT] ----------
// Blocks [0,1024): conv (b, 4-channel group).  Blocks [1024,3072): FFT pair (skipped if unused).
__global__ __launch_bounds__(512, 2) void k1_fft_conv(const float* __restrict__ x,
                                                      const float* __restrict__ cw,
                                                      const float* __restrict__ fbs) {
    __shared__ __align__(16) char sh[FFT_SM_F2 * 8 + 512];
    __shared__ int s_flag;
    const int tid = threadIdx.x;

    if (blockIdx.x < 1024) {
        // ---- conv path: 4 channels, padded stride-72 layout, float4 fills ----
        float* sp = (float*)sh;            // 66 rows x 72 floats = 19008 B
        float* sw = (float*)(sh + 19008);  // 36 floats
        const int idx = blockIdx.x;
        const int b = idx & 63, cg = idx >> 6;
        const int c0 = cg * 4;
        const int ww = tid & 63, hb8 = (tid >> 6) * 8;
        for (int k = tid; k < 66 * 72; k += 512) sp[k] = 0.f;
        for (int k = tid; k < 36; k += 512) sw[k] = cw[c0 * 9 + k];
        ull acc2[4];
#pragma unroll
        for (int q = 0; q < 4; q++) acc2[q] = PK(0.f, 0.f);
        const float4* xb4 = (const float4*)(x + ((size_t)b * 64 + c0) * 4096);
#pragma unroll
        for (int c = 0; c < 4; c++) {
            __syncthreads();
#pragma unroll
            for (int k = tid; k < 1024; k += 512) {
                int row = k >> 4, q4 = (k & 15) * 4;
                *(float4*)&sp[(row + 1) * 72 + 4 + q4] = xb4[c * 1024 + k];
            }
            __syncthreads();
            ull wd[9];
#pragma unroll
            for (int j = 0; j < 9; j++) {
                float wv = sw[c * 9 + j];
                wd[j] = PK(wv, wv);
            }
#pragma unroll
            for (int kw = 0; kw < 3; kw++) {
                float wcol[10];
#pragma unroll
                for (int rr = 0; rr < 10; rr++) wcol[rr] = sp[(hb8 + rr) * 72 + 3 + ww + kw];
                ull pkc[6];
#pragma unroll
                for (int j = 0; j < 6; j++) pkc[j] = PK(wcol[j], wcol[j + 4]);
#pragma unroll
                for (int q = 0; q < 4; q++)
#pragma unroll
                    for (int kh = 0; kh < 3; kh++)
                        acc2[q] = PFMA(pkc[q + kh], wd[kh * 3 + kw], acc2[q]);
            }
        }
        float* o = d_sp4 + ((size_t)cg * 64 + b) * 4096;
#pragma unroll
        for (int q = 0; q < 4; q++) {
            float2 a = UPK(acc2[q]);
            o[(hb8 + q) * 64 + ww] = a.x;
            o[(hb8 + q + 4) * 64 + ww] = a.y;
        }
    } else {
        const int fb = blockIdx.x - 1024;
        const int b = fb >> 5;
        if (!batch_needed(fbs, b, tid, &s_flag)) return;  // dead magnitudes
        float2* sm = (float2*)sh;
        float2* s_tw = (float2*)(sh + FFT_SM_F2 * 8);
        const int i0 = (fb & 31) * 2;
        if (tid < 64) {
            float sn, cs;
            __sincosf(-6.283185307179586f * (float)tid * (1.0f / 64.0f), &sn, &cs);
            s_tw[tid] = make_float2(cs, sn);
        }
        __syncthreads();
        const float* xp0 = x + ((size_t)(b * 64 + i0)) * 4096;
        const float* xp1 = xp0 + 4096;
        {
            const int g = tid >> 3, t = tid & 7;
            ull v[8];
#pragma unroll
            for (int n1 = 0; n1 < 8; n1++) {
                int idx = g * 64 + 8 * n1 + t;
                v[n1] = PK(xp0[idx], xp1[idx]);
            }
            row_pass_reg<-1>(v, sm, s_tw, tid);
        }
        __syncthreads();
        fft_pass<-1, false>(sm, s_tw, tid);
        __syncthreads();
        // Hermitian split magnitudes, half2 stores (column pairs per thread)
        __half2* m0 = (__half2*)(d_Mh + ((size_t)(b * 64 + i0)) * 4096);
        __half2* m1 = m0 + 2048;
#pragma unroll
        for (int n = 0; n < 4; n++) {
            int e = tid + n * 512;              // 0..2047
            int r = e >> 5, cp = (e & 31) * 2;  // columns cp, cp+1
            int rm = (64 - r) & 63;
            int cm0 = (64 - cp) & 63, cm1 = (63 - cp) & 63;
            float2 Za = sm[fft_phys(r, cp)];
            float2 Zb = sm[fft_phys(r, cp + 1)];
            float2 Ma = sm[fft_phys(rm, cm0)];
            float2 Mb = sm[fft_phys(rm, cm1)];
            float sax = Za.x + Ma.x, say = Za.y - Ma.y;
            float dax = Za.x - Ma.x, day = Za.y + Ma.y;
            float sbx = Zb.x + Mb.x, sby = Zb.y - Mb.y;
            float dbx = Zb.x - Mb.x, dby = Zb.y + Mb.y;
            m0[e] = __floats2half2_rn(0.5f * sqrtf(sax * sax + say * say),
                                      0.5f * sqrtf(sbx * sbx + sby * sby));
            m1[e] = __floats2half2_rn(0.5f * sqrtf(dax * dax + day * day),
                                      0.5f * sqrtf(dbx * dbx + dby * dby));
        }
    }
}

// ---------------- kernel 2: [conv reduce + conv-only out stream (64 blocks)] + [attention] ------
// Blocks [0,64): reduce partials for batch b, write d_sp AND write c1*conv to ALL 64 out planes.
// Blocks [64,1088): attention tile (skipped if i unused).
__global__ __launch_bounds__(256, 2) void attn_kernel(
    const float* __restrict__ f0, const float* __restrict__ theta,
    const float* __restrict__ sigma, const float* __restrict__ theta0,
    const float* __restrict__ w1, const float* __restrict__ b1,
    const float* __restrict__ w2, const float* __restrict__ b2,
    const float* __restrict__ fbs, const float* __restrict__ mixp,
    float* __restrict__ out) {
    const int tid = threadIdx.x;
    if (blockIdx.x < 64) {  // conv reduce + out stream
        const int b = blockIdx.x;
        const float c1 = 1.f - mixp[0];
        const float4* A = ((const float4*)d_sp4) + (size_t)b * 1024;
        float4* O = ((float4*)d_sp) + (size_t)b * 1024;
        float4* ob = ((float4*)out) + (size_t)b * 65536;
#pragma unroll
        for (int q = tid; q < 1024; q += 256) {
            float4 s = A[q];
#pragma unroll
            for (int j = 1; j < 16; j++) {
                float4 p = A[q + j * 65536];
                s.x += p.x; s.y += p.y; s.z += p.z; s.w += p.w;
            }
            O[q] = s;
            float4 w = make_float4(c1 * s.x, c1 * s.y, c1 * s.z, c1 * s.w);
#pragma unroll 4
            for (int i = 0; i < 64; i++) ob[i * 1024 + q] = w;
        }
        return;
    }
    __shared__ int s_flag;
    const int i = (blockIdx.x - 64) >> 4;
    if (!batch_needed(fbs, i, tid, &s_flag)) return;  // G[i] never read
    __shared__ __align__(16) __half sA[64 * 72];
    __shared__ __align__(16) __half sM[64 * 264];
    __shared__ float s_w2[3 * 64];
    __shared__ float s_b1[64];
    __shared__ float s_lf0[3], s_i2ls2[3], s_th[3], s_i2t02[3], s_b2[3];
    const int pbeg = ((blockIdx.x - 64) & 15) * 256;

    for (int k = tid; k < 4096; k += 256) {
        int o = k >> 6, c = k & 63;
        sA[o * 72 + c] = __float2half(w1[o * 64 + ((c + 32) & 63)]);
    }
    for (int t = tid; t < 2048; t += 256) {
        int c = t >> 5, q = t & 31;
        uint4 v = *(const uint4*)(d_Mh + ((size_t)(i * 64 + c)) * 4096 + pbeg + q * 8);
        *(uint4*)&sM[c * 264 + q * 8] = v;
    }
    if (tid < 64) s_b1[tid] = b1[tid];
    if (tid < 192) s_w2[tid] = w2[tid];
    if (tid < 3) {
        s_b2[tid] = b2[tid];
        int ip = (i + 32) & 63;
        int idx = tid * 64 + ip;
        s_lf0[tid] = logf(f0[idx]);
        float ls = logf(sigma[idx]);
        s_i2ls2[tid] = 1.f / (2.f * ls * ls);
        s_th[tid] = theta[idx];
        float t0v = theta0[idx];
        s_i2t02[tid] = 1.f / (2.f * t0v * t0v);
    }
    __syncthreads();

    const int wid = tid >> 5, lane = tid & 31;
    const int o0 = (wid & 3) << 4, pw = (wid >> 2) << 7;
    const uint32_t sA_addr = (uint32_t)__cvta_generic_to_shared(sA);
    const uint32_t sM_addr = (uint32_t)__cvta_generic_to_shared(sM);

    uint32_t a[4][4];
#pragma unroll
    for (int ks = 0; ks < 4; ks++) {
        uint32_t addr = sA_addr + (uint32_t)(((o0 + (lane & 15)) * 72 + ks * 16 + ((lane >> 4) << 3)) * 2);
        ldsm_x4(a[ks], addr);
    }
    float acc[16][4];
#pragma unroll
    for (int j = 0; j < 16; j++)
#pragma unroll
        for (int q = 0; q < 4; q++) acc[j][q] = 0.f;
#pragma unroll
    for (int j = 0; j < 16; j++) {
#pragma unroll
        for (int ks = 0; ks < 4; ks++) {
            uint32_t b[2];
            uint32_t addr = sM_addr + (uint32_t)(((ks * 16 + (lane & 15)) * 264 + pw + j * 8) * 2);
            ldsm_x2_trans(b, addr);
            mma16816(acc[j], a[ks], b);
        }
    }
    __syncthreads();

    {
        const int r0 = o0 + (lane >> 2);
        const int cbase = pw + (lane & 3) * 2;
        float b1a = s_b1[r0], b1b = s_b1[r0 + 8];
#pragma unroll
        for (int j = 0; j < 16; j++) {
            int c = cbase + j * 8;
            *(__half2*)&sM[r0 * 264 + c] =
                __floats2half2_rn(fmaxf(acc[j][0] + b1a, 0.f), fmaxf(acc[j][1] + b1a, 0.f));
            *(__half2*)&sM[(r0 + 8) * 264 + c] =
                __floats2half2_rn(fmaxf(acc[j][2] + b1b, 0.f), fmaxf(acc[j][3] + b1b, 0.f));
        }
    }
    __syncthreads();

    {
        float l0 = s_b2[0], l1 = s_b2[1], l2 = s_b2[2];
#pragma unroll
        for (int o = 0; o < 64; o++) {
            float hv = __half2float(sM[o * 264 + tid]);
            l0 = fmaf(s_w2[o], hv, l0);
            l1 = fmaf(s_w2[64 + o], hv, l1);
            l2 = fmaf(s_w2[128 + o], hv, l2);
        }
        float mx = fmaxf(l0, fmaxf(l1, l2));
        float e0 = __expf(l0 - mx), e1 = __expf(l1 - mx), e2 = __expf(l2 - mx);
        float inv = 1.f / (e0 + e1 + e2);
        const int p = pbeg + tid;
        int hh = ((p >> 6) + 32) & 63;
        int ww = ((p & 63) + 32) & 63;
        float yv_ = -1.f + 2.f * (float)hh * (1.f / 63.f);
        float xv_ = -1.f + 2.f * (float)ww * (1.f / 63.f);
        float r2 = xv_ * xv_ + yv_ * yv_ + 1e-6f;
        float lr = 0.5f * logf(r2);
        float phi = atan2f(yv_, xv_);
        float G = 0.f;
        float awv[3] = {e0 * inv, e1 * inv, e2 * inv};
#pragma unroll
        for (int s = 0; s < 3; s++) {
            float dl = lr - s_lf0[s];
            float dp = phi - s_th[s];
            float F = __expf(-(dl * dl) * s_i2ls2[s] - (dp * dp) * s_i2t02[s]);
            G = fmaf(F, awv[s], G);
        }
        d_G[i * 4096 + p] = G;
    }
}

// ---------------- kernel 3: survivors only — two-for-one filter + IFFT, overwrite out ------------
__global__ __launch_bounds__(512, 2) void inv_kernel(const float* __restrict__ x,
                                                     const float* __restrict__ fbs,
                                                     const float* __restrict__ mixp,
                                                     float* __restrict__ out) {
    __shared__ float2 sm[FFT_SM_F2];
    __shared__ float2 s_tw[64];
    const int plane = blockIdx.x;
    const int b = plane >> 6, i = plane & 63;
    const int tid = threadIdx.x;
    const int bb = (b + 32) & 63;
    const int si = (int)floorf((fbs[bb * 2 + 0] + 1.f) * 0.5f * 64.f);
    const int ei = (int)floorf((fbs[bb * 2 + 1] + 1.f) * 0.5f * 64.f);
    const int ii = (i + 32) & 63;
    if (!(ii >= si && ii < ei)) return;     // conv-only planes already written by attn
    const int j = ii - si;
    if (j & 1) return;                      // handled by partner block (i-1)
    const bool haspart = (ii + 1 < ei);
    const float mix = mixp[0];
    const float c1 = 1.f - mix;
    const float4* sb4 = ((const float4*)d_sp) + (size_t)b * 1024;

    if (tid < 64) {
        float sn, cs;
        __sincosf(-6.283185307179586f * (float)tid * (1.0f / 64.0f), &sn, &cs);
        s_tw[tid] = make_float2(cs, sn);
    }
    __syncthreads();
    const float* xp0 = x + (size_t)plane * 4096;
    const float* xp1 = xp0 + 4096;
    {
        const int g = tid >> 3, t = tid & 7;
        ull v[8];
#pragma unroll
        for (int n1 = 0; n1 < 8; n1++) {
            int idx = g * 64 + 8 * n1 + t;
            v[n1] = PK(xp0[idx], haspart ? xp1[idx] : 0.f);
        }
        row_pass_reg<-1>(v, sm, s_tw, tid);
    }
    __syncthreads();
    fft_pass<-1, false>(sm, s_tw, tid);
    __syncthreads();
    const float* G0 = d_G + i * 4096;
    const float* G1 = d_G + (i + 1) * 4096;
    float2 P[8];
#pragma unroll
    for (int n = 0; n < 8; n++) {
        int k = tid + n * 512;
        int r = k >> 6, c = k & 63;
        int rm = (64 - r) & 63, cm = (64 - c) & 63;
        int km = rm * 64 + cm;
        float2 Zk = sm[fft_phys(r, c)];
        float2 Zm = sm[fft_phys(rm, cm)];
        int hh = (r + 32) & 63, hhm = (rm + 32) & 63;
        float mr = (hh >= si && hh < ei) ? 0.5f : 0.f;
        float mrm = (hhm >= si && hhm < ei) ? 0.5f : 0.f;
        float g0 = G0[k] * mr + G0[km] * mrm;
        float g1 = haspart ? (G1[k] * mr + G1[km] * mrm) : 0.f;
        float y0x = 0.5f * (Zk.x + Zm.x), y0y = 0.5f * (Zk.y - Zm.y);
        float y1x = 0.5f * (Zk.y + Zm.y), y1y = -0.5f * (Zk.x - Zm.x);
        P[n] = make_float2(y0x * g0 - g1 * y1y, y0y * g0 + g1 * y1x);
    }
    __syncthreads();
#pragma unroll
    for (int n = 0; n < 8; n++) {
        int k = tid + n * 512;
        sm[fft_phys(k >> 6, k & 63)] = P[n];
    }
    __syncthreads();
    fft_pass<1, true>(sm, s_tw, tid);
    __syncthreads();
    fft_pass<1, false>(sm, s_tw, tid);
    __syncthreads();
    const float scale = mix * (1.f / 4096.f);
    float4* op0 = (float4*)(out + (size_t)plane * 4096);
    float4* op1 = (float4*)(out + (size_t)(plane + 1) * 4096);
#pragma unroll
    for (int q = tid; q < 1024; q += 512) {
        int r = q >> 4, c = (q & 15) * 4;
        float2 w0 = sm[fft_phys(r, c + 0)];
        float2 w1v = sm[fft_phys(r, c + 1)];
        float2 w2v = sm[fft_phys(r, c + 2)];
        float2 w3 = sm[fft_phys(r, c + 3)];
        float4 s = sb4[q];
        op0[q] = make_float4(fmaf(scale, w0.x, c1 * s.x), fmaf(scale, w1v.x, c1 * s.y),
                             fmaf(scale, w2v.x, c1 * s.z), fmaf(scale, w3.x, c1 * s.w));
        if (haspart)
            op1[q] = make_float4(fmaf(scale, w0.y, c1 * s.x), fmaf(scale, w1v.y, c1 * s.y),
                                 fmaf(scale, w2v.y, c1 * s.z), fmaf(scale, w3.y, c1 * s.w));
    }
}

// ---------------- launch ----------------
extern "C" void kernel_launch(void* const* d_in, const int* in_sizes, int n_in,
                              void* d_out, int out_size) {
    const float* x      = (const float*)d_in[0];
    const float* f0     = (const float*)d_in[1];
    const float* theta  = (const float*)d_in[2];
    const float* sigma  = (const float*)d_in[3];
    const float* theta0 = (const float*)d_in[4];
    const float* fbs    = (const float*)d_in[5];
    const float* mix    = (const float*)d_in[6];
    const float* w1     = (const float*)d_in[7];
    const float* b1     = (const float*)d_in[8];
    const float* w2     = (const float*)d_in[9];
    const float* b2     = (const float*)d_in[10];
    const float* conv_w = (const float*)d_in[11];
    float* out = (float*)d_out;

    k1_fft_conv<<<3072, 512>>>(x, conv_w, fbs);
    attn_kernel<<<1088, 256>>>(f0, theta, sigma, theta0, w1, b1, w2, b2, fbs, mix, out);
    inv_kernel<<<4096, 512>>>(x, fbs, mix, out);
}

// round 17
// speedup vs baseline: 1.0634x; 1.0634x over previous
#include <cuda_runtime.h>
#include <cuda_fp16.h>
#include <math.h>
#include <stdint.h>

typedef unsigned long long ull;

// ---------------- device scratch (no allocs allowed) ----------------
__device__ __align__(16) __half d_Mh[4096ull * 4096ull];  // |FFT| magnitudes, fp16, 32MB
__device__ __align__(16) __half d_w1h[4096];              // channel-rolled w1, fp16
__device__ float d_G[64 * 4096];                          // G'[i,h,w], 1MB
__device__ float d_sp4[16 * 64 * 4096];                   // conv partials (16 groups), 16MB
__device__ float d_sp[64 * 4096];                         // reduced conv, 1MB

// ---------------- packed f32x2 helpers ----------------
__device__ __forceinline__ ull PK(float x, float y) {
    ull r; asm("mov.b64 %0,{%1,%2};" : "=l"(r) : "f"(x), "f"(y)); return r;
}
__device__ __forceinline__ float2 UPK(ull v) {
    float2 r; asm("mov.b64 {%0,%1},%2;" : "=f"(r.x), "=f"(r.y) : "l"(v)); return r;
}
__device__ __forceinline__ ull PADD(ull a, ull b) {
    ull d; asm("add.rn.f32x2 %0,%1,%2;" : "=l"(d) : "l"(a), "l"(b)); return d;
}
__device__ __forceinline__ ull PFMA(ull a, ull b, ull c) {
    ull d; asm("fma.rn.f32x2 %0,%1,%2,%3;" : "=l"(d) : "l"(a), "l"(b), "l"(c)); return d;
}
__device__ __forceinline__ ull PSUB(ull a, ull b) {
    return PFMA(b, PK(-1.f, -1.f), a);
}

// ---------------- MMA helpers ----------------
__device__ __forceinline__ void ldsm_x4(uint32_t (&r)[4], uint32_t addr) {
    asm volatile("ldmatrix.sync.aligned.m8n8.x4.shared.b16 {%0,%1,%2,%3}, [%4];"
                 : "=r"(r[0]), "=r"(r[1]), "=r"(r[2]), "=r"(r[3]) : "r"(addr));
}
__device__ __forceinline__ void ldsm_x2_trans(uint32_t (&r)[2], uint32_t addr) {
    asm volatile("ldmatrix.sync.aligned.m8n8.x2.trans.shared.b16 {%0,%1}, [%2];"
                 : "=r"(r[0]), "=r"(r[1]) : "r"(addr));
}
__device__ __forceinline__ void mma16816(float (&d)[4], const uint32_t (&a)[4], const uint32_t (&b)[2]) {
    asm volatile(
        "mma.sync.aligned.m16n8k16.row.col.f32.f16.f16.f32 "
        "{%0,%1,%2,%3},{%4,%5,%6,%7},{%8,%9},{%0,%1,%2,%3};"
        : "+f"(d[0]), "+f"(d[1]), "+f"(d[2]), "+f"(d[3])
        : "r"(a[0]), "r"(a[1]), "r"(a[2]), "r"(a[3]), "r"(b[0]), "r"(b[1]));
}

// ---------------- FFT smem layout ----------------
#define FFT_SM_F2 (64 * 72)
__device__ __forceinline__ int fft_phys(int r, int c) { return r * 72 + (c ^ (r & 7)); }

// 8-point DIF FFT on packed complex (re,im) in f32x2 registers. SGN=-1 fwd, +1 inv.
template <int SGN>
__device__ __forceinline__ void fft8p(ull v[8]) {
    const float S = (float)SGN;
    const float C = 0.70710678118654752440f;
    ull t0 = PADD(v[0], v[4]), t4 = PSUB(v[0], v[4]);
    ull t1 = PADD(v[1], v[5]), t5 = PSUB(v[1], v[5]);
    ull t2 = PADD(v[2], v[6]), t6 = PSUB(v[2], v[6]);
    ull t3 = PADD(v[3], v[7]), t7 = PSUB(v[3], v[7]);
    float2 f5 = UPK(t5), f6 = UPK(t6), f7 = UPK(t7);
    t5 = PK(C * (f5.x - S * f5.y), C * (S * f5.x + f5.y));
    t6 = PK(-S * f6.y, S * f6.x);
    t7 = PK(C * (-f7.x - S * f7.y), C * (S * f7.x - f7.y));
    ull u0 = PADD(t0, t2), u2 = PSUB(t0, t2);
    ull u1 = PADD(t1, t3);
    float2 d13 = UPK(PSUB(t1, t3));
    ull u3 = PK(-S * d13.y, S * d13.x);
    ull u4 = PADD(t4, t6), u6 = PSUB(t4, t6);
    ull u5 = PADD(t5, t7);
    float2 d57 = UPK(PSUB(t5, t7));
    ull u7 = PK(-S * d57.y, S * d57.x);
    v[0] = PADD(u0, u1); v[4] = PSUB(u0, u1);
    v[2] = PADD(u2, u3); v[6] = PSUB(u2, u3);
    v[1] = PADD(u4, u5); v[5] = PSUB(u4, u5);
    v[3] = PADD(u6, u7); v[7] = PSUB(u6, u7);
}

__device__ __forceinline__ ull tw_mul(ull z, float2 w) {
    float2 f = UPK(z);
    return PK(f.x * w.x - f.y * w.y, f.x * w.y + f.y * w.x);
}

// Row pass with input already in registers (v[n1] = z[g][8*n1+t]).
template <int SGN>
__device__ __forceinline__ void row_pass_reg(ull v[8], float2* smf, const float2* s_tw, int tid) {
    ull* sm = (ull*)smf;
    const int g = tid >> 3, t = tid & 7;
    fft8p<SGN>(v);
#pragma unroll
    for (int k1 = 1; k1 < 8; k1++) {
        float2 w = s_tw[(t * k1) & 63];
        if (SGN == 1) w.y = -w.y;
        v[k1] = tw_mul(v[k1], w);
    }
    __syncwarp();
#pragma unroll
    for (int k1 = 0; k1 < 8; k1++) sm[fft_phys(g, 8 * k1 + (t ^ k1))] = v[k1];
    __syncwarp();
#pragma unroll
    for (int n2 = 0; n2 < 8; n2++) v[n2] = sm[fft_phys(g, 8 * t + (n2 ^ t))];
    fft8p<SGN>(v);
    __syncwarp();
#pragma unroll
    for (int k2 = 0; k2 < 8; k2++) sm[fft_phys(g, t + 8 * k2)] = v[k2];
}

// One pass (rows or cols) of a 64x64 2D FFT in shared memory (LDS-sourced).
template <int SGN, bool ROWS>
__device__ __forceinline__ void fft_pass(float2* smf, const float2* s_tw, int tid) {
    ull* sm = (ull*)smf;
    const int g = tid >> 3;
    const int t = tid & 7;
#define LIDX(m) (ROWS ? fft_phys(g, (m)) : fft_phys((m), g))
    ull v[8];
#pragma unroll
    for (int n1 = 0; n1 < 8; n1++) v[n1] = sm[LIDX(8 * n1 + t)];
    fft8p<SGN>(v);
#pragma unroll
    for (int k1 = 1; k1 < 8; k1++) {
        float2 w = s_tw[(t * k1) & 63];
        if (SGN == 1) w.y = -w.y;
        v[k1] = tw_mul(v[k1], w);
    }
    __syncwarp();
#pragma unroll
    for (int k1 = 0; k1 < 8; k1++) sm[LIDX(8 * k1 + (t ^ k1))] = v[k1];
    __syncwarp();
#pragma unroll
    for (int n2 = 0; n2 < 8; n2++) v[n2] = sm[LIDX(8 * t + (n2 ^ t))];
    fft8p<SGN>(v);
    __syncwarp();
#pragma unroll
    for (int k2 = 0; k2 < 8; k2++) sm[LIDX(t + 8 * k2)] = v[k2];
#undef LIDX
}

// needed(B): does G[B] (built from batch-B magnitudes) feed any surviving plane?
__device__ __forceinline__ bool batch_needed(const float* __restrict__ fbs, int B,
                                             int tid, int* s_flag) {
    if (tid == 0) *s_flag = 0;
    __syncthreads();
    if (tid < 64) {
        int si = (int)floorf((fbs[tid * 2 + 0] + 1.f) * 0.5f * 64.f);
        int ei = (int)floorf((fbs[tid * 2 + 1] + 1.f) * 0.5f * 64.f);
        int iB = (B + 32) & 63;
        if (iB >= si && iB < ei) *s_flag = 1;
    }
    __syncthreads();
    return *s_flag != 0;
}

// ---------------- kernel 1: fused [3x3 conv partials] + [two-for-one fwd FFT] + [w1 prep] -------
// Blocks [0,1024): conv (b, 4-channel group).  Blocks [1024,3072): FFT pair (skipped if unused).
// Block 3072: w1 -> fp16 channel-rolled prep.
__global__ __launch_bounds__(512, 2) void k1_fft_conv(const float* __restrict__ x,
                                                      const float* __restrict__ cw,
                                                      const float* __restrict__ fbs,
                                                      const float* __restrict__ w1) {
    __shared__ __align__(16) char sh[FFT_SM_F2 * 8 + 512];
    __shared__ int s_flag;
    const int tid = threadIdx.x;

    if (blockIdx.x < 1024) {
        // ---- conv path: 4 channels, padded stride-72 layout, float4 fills ----
        float* sp = (float*)sh;            // 66 rows x 72 floats = 19008 B
        float* sw = (float*)(sh + 19008);  // 36 floats
        const int idx = blockIdx.x;
        const int b = idx & 63, cg = idx >> 6;
        const int c0 = cg * 4;
        const int ww = tid & 63, hb8 = (tid >> 6) * 8;
        for (int k = tid; k < 66 * 72; k += 512) sp[k] = 0.f;
        for (int k = tid; k < 36; k += 512) sw[k] = cw[c0 * 9 + k];
        ull acc2[4];
#pragma unroll
        for (int q = 0; q < 4; q++) acc2[q] = PK(0.f, 0.f);
        const float4* xb4 = (const float4*)(x + ((size_t)b * 64 + c0) * 4096);
#pragma unroll
        for (int c = 0; c < 4; c++) {
            __syncthreads();
#pragma unroll
            for (int k = tid; k < 1024; k += 512) {
                int row = k >> 4, q4 = (k & 15) * 4;
                *(float4*)&sp[(row + 1) * 72 + 4 + q4] = xb4[c * 1024 + k];
            }
            __syncthreads();
            ull wd[9];
#pragma unroll
            for (int j = 0; j < 9; j++) {
                float wv = sw[c * 9 + j];
                wd[j] = PK(wv, wv);
            }
#pragma unroll
            for (int kw = 0; kw < 3; kw++) {
                float wcol[10];
#pragma unroll
                for (int rr = 0; rr < 10; rr++) wcol[rr] = sp[(hb8 + rr) * 72 + 3 + ww + kw];
                ull pkc[6];
#pragma unroll
                for (int j = 0; j < 6; j++) pkc[j] = PK(wcol[j], wcol[j + 4]);
#pragma unroll
                for (int q = 0; q < 4; q++)
#pragma unroll
                    for (int kh = 0; kh < 3; kh++)
                        acc2[q] = PFMA(pkc[q + kh], wd[kh * 3 + kw], acc2[q]);
            }
        }
        float* o = d_sp4 + ((size_t)cg * 64 + b) * 4096;
#pragma unroll
        for (int q = 0; q < 4; q++) {
            float2 a = UPK(acc2[q]);
            o[(hb8 + q) * 64 + ww] = a.x;
            o[(hb8 + q + 4) * 64 + ww] = a.y;
        }
    } else if (blockIdx.x < 3072) {
        const int fb = blockIdx.x - 1024;
        const int b = fb >> 5;
        if (!batch_needed(fbs, b, tid, &s_flag)) return;  // dead magnitudes
        float2* sm = (float2*)sh;
        float2* s_tw = (float2*)(sh + FFT_SM_F2 * 8);
        const int i0 = (fb & 31) * 2;
        if (tid < 64) {
            float sn, cs;
            __sincosf(-6.283185307179586f * (float)tid * (1.0f / 64.0f), &sn, &cs);
            s_tw[tid] = make_float2(cs, sn);
        }
        __syncthreads();
        const float* xp0 = x + ((size_t)(b * 64 + i0)) * 4096;
        const float* xp1 = xp0 + 4096;
        {
            const int g = tid >> 3, t = tid & 7;
            ull v[8];
#pragma unroll
            for (int n1 = 0; n1 < 8; n1++) {
                int idx = g * 64 + 8 * n1 + t;
                v[n1] = PK(xp0[idx], xp1[idx]);
            }
            row_pass_reg<-1>(v, sm, s_tw, tid);
        }
        __syncthreads();
        fft_pass<-1, false>(sm, s_tw, tid);
        __syncthreads();
        // Hermitian split magnitudes, half2 stores (column pairs per thread)
        __half2* m0 = (__half2*)(d_Mh + ((size_t)(b * 64 + i0)) * 4096);
        __half2* m1 = m0 + 2048;
#pragma unroll
        for (int n = 0; n < 4; n++) {
            int e = tid + n * 512;              // 0..2047
            int r = e >> 5, cp = (e & 31) * 2;  // columns cp, cp+1
            int rm = (64 - r) & 63;
            int cm0 = (64 - cp) & 63, cm1 = (63 - cp) & 63;
            float2 Za = sm[fft_phys(r, cp)];
            float2 Zb = sm[fft_phys(r, cp + 1)];
            float2 Ma = sm[fft_phys(rm, cm0)];
            float2 Mb = sm[fft_phys(rm, cm1)];
            float sax = Za.x + Ma.x, say = Za.y - Ma.y;
            float dax = Za.x - Ma.x, day = Za.y + Ma.y;
            float sbx = Zb.x + Mb.x, sby = Zb.y - Mb.y;
            float dbx = Zb.x - Mb.x, dby = Zb.y + Mb.y;
            m0[e] = __floats2half2_rn(0.5f * sqrtf(sax * sax + say * say),
                                      0.5f * sqrtf(sbx * sbx + sby * sby));
            m1[e] = __floats2half2_rn(0.5f * sqrtf(dax * dax + day * day),
                                      0.5f * sqrtf(dbx * dbx + dby * dby));
        }
    } else {
        // ---- w1 prep: fp16 convert with channel roll ----
        for (int k = tid; k < 4096; k += 512) {
            int o = k >> 6, c = k & 63;
            d_w1h[k] = __float2half(w1[o * 64 + ((c + 32) & 63)]);
        }
    }
}

// ---------------- kernel 2: [conv reduce + conv-only out stream (64 blocks)] + [attention] ------
// Blocks [0,64): reduce partials for batch b, write d_sp AND write c1*conv to all non-survivor
//   out planes of batch b (survivors are fully overwritten by inv).
// Blocks [64,1088): attention tile (skipped if i unused).
__global__ __launch_bounds__(256, 2) void attn_kernel(
    const float* __restrict__ f0, const float* __restrict__ theta,
    const float* __restrict__ sigma, const float* __restrict__ theta0,
    const float* __restrict__ b1, const float* __restrict__ w2,
    const float* __restrict__ b2,
    const float* __restrict__ fbs, const float* __restrict__ mixp,
    float* __restrict__ out) {
    const int tid = threadIdx.x;
    if (blockIdx.x < 64) {  // conv reduce + out stream
        const int b = blockIdx.x;
        const float c1 = 1.f - mixp[0];
        const int bb = (b + 32) & 63;
        const int si = (int)floorf((fbs[bb * 2 + 0] + 1.f) * 0.5f * 64.f);
        const int ei = (int)floorf((fbs[bb * 2 + 1] + 1.f) * 0.5f * 64.f);
        const float4* A = ((const float4*)d_sp4) + (size_t)b * 1024;
        float4* O = ((float4*)d_sp) + (size_t)b * 1024;
        float4* ob = ((float4*)out) + (size_t)b * 65536;
#pragma unroll
        for (int q = tid; q < 1024; q += 256) {
            float4 s = A[q];
#pragma unroll
            for (int j = 1; j < 16; j++) {
                float4 p = A[q + j * 65536];
                s.x += p.x; s.y += p.y; s.z += p.z; s.w += p.w;
            }
            O[q] = s;
            float4 w = make_float4(c1 * s.x, c1 * s.y, c1 * s.z, c1 * s.w);
            for (int i = 0; i < 64; i++) {
                int ii = (i + 32) & 63;
                if (ii >= si && ii < ei) continue;  // survivor: inv overwrites fully
                ob[i * 1024 + q] = w;
            }
        }
        return;
    }
    __shared__ int s_flag;
    const int i = (blockIdx.x - 64) >> 4;
    if (!batch_needed(fbs, i, tid, &s_flag)) return;  // G[i] never read
    __shared__ __align__(16) __half sA[64 * 72];
    __shared__ __align__(16) __half sM[64 * 264];
    __shared__ float s_w2[3 * 64];
    __shared__ float s_b1[64];
    __shared__ float s_lf0[3], s_i2ls2[3], s_th[3], s_i2t02[3], s_b2[3];
    const int pbeg = ((blockIdx.x - 64) & 15) * 256;

    // sA from prepped fp16 (uint4 copies)
    {
        const uint4* src = (const uint4*)d_w1h;
        for (int t = tid; t < 512; t += 256) {
            int o = t >> 3, cc = (t & 7) * 8;
            *(uint4*)&sA[o * 72 + cc] = src[t];
        }
    }
    for (int t = tid; t < 2048; t += 256) {
        int c = t >> 5, q = t & 31;
        uint4 v = *(const uint4*)(d_Mh + ((size_t)(i * 64 + c)) * 4096 + pbeg + q * 8);
        *(uint4*)&sM[c * 264 + q * 8] = v;
    }
    if (tid < 64) s_b1[tid] = b1[tid];
    if (tid < 192) s_w2[tid] = w2[tid];
    if (tid < 3) {
        s_b2[tid] = b2[tid];
        int ip = (i + 32) & 63;
        int idx = tid * 64 + ip;
        s_lf0[tid] = logf(f0[idx]);
        float ls = logf(sigma[idx]);
        s_i2ls2[tid] = 1.f / (2.f * ls * ls);
        s_th[tid] = theta[idx];
        float t0v = theta0[idx];
        s_i2t02[tid] = 1.f / (2.f * t0v * t0v);
    }
    __syncthreads();

    const int wid = tid >> 5, lane = tid & 31;
    const int o0 = (wid & 3) << 4, pw = (wid >> 2) << 7;
    const uint32_t sA_addr = (uint32_t)__cvta_generic_to_shared(sA);
    const uint32_t sM_addr = (uint32_t)__cvta_generic_to_shared(sM);

    uint32_t a[4][4];
#pragma unroll
    for (int ks = 0; ks < 4; ks++) {
        uint32_t addr = sA_addr + (uint32_t)(((o0 + (lane & 15)) * 72 + ks * 16 + ((lane >> 4) << 3)) * 2);
        ldsm_x4(a[ks], addr);
    }
    float acc[16][4];
#pragma unroll
    for (int j = 0; j < 16; j++)
#pragma unroll
        for (int q = 0; q < 4; q++) acc[j][q] = 0.f;
#pragma unroll
    for (int j = 0; j < 16; j++) {
#pragma unroll
        for (int ks = 0; ks < 4; ks++) {
            uint32_t b[2];
            uint32_t addr = sM_addr + (uint32_t)(((ks * 16 + (lane & 15)) * 264 + pw + j * 8) * 2);
            ldsm_x2_trans(b, addr);
            mma16816(acc[j], a[ks], b);
        }
    }
    __syncthreads();

    {
        const int r0 = o0 + (lane >> 2);
        const int cbase = pw + (lane & 3) * 2;
        float b1a = s_b1[r0], b1b = s_b1[r0 + 8];
#pragma unroll
        for (int j = 0; j < 16; j++) {
            int c = cbase + j * 8;
            *(__half2*)&sM[r0 * 264 + c] =
                __floats2half2_rn(fmaxf(acc[j][0] + b1a, 0.f), fmaxf(acc[j][1] + b1a, 0.f));
            *(__half2*)&sM[(r0 + 8) * 264 + c] =
                __floats2half2_rn(fmaxf(acc[j][2] + b1b, 0.f), fmaxf(acc[j][3] + b1b, 0.f));
        }
    }
    __syncthreads();

    {
        float l0 = s_b2[0], l1 = s_b2[1], l2 = s_b2[2];
#pragma unroll
        for (int o = 0; o < 64; o++) {
            float hv = __half2float(sM[o * 264 + tid]);
            l0 = fmaf(s_w2[o], hv, l0);
            l1 = fmaf(s_w2[64 + o], hv, l1);
            l2 = fmaf(s_w2[128 + o], hv, l2);
        }
        float mx = fmaxf(l0, fmaxf(l1, l2));
        float e0 = __expf(l0 - mx), e1 = __expf(l1 - mx), e2 = __expf(l2 - mx);
        float inv = 1.f / (e0 + e1 + e2);
        const int p = pbeg + tid;
        int hh = ((p >> 6) + 32) & 63;
        int ww = ((p & 63) + 32) & 63;
        float yv_ = -1.f + 2.f * (float)hh * (1.f / 63.f);
        float xv_ = -1.f + 2.f * (float)ww * (1.f / 63.f);
        float r2 = xv_ * xv_ + yv_ * yv_ + 1e-6f;
        float lr = 0.5f * logf(r2);
        float phi = atan2f(yv_, xv_);
        float G = 0.f;
        float awv[3] = {e0 * inv, e1 * inv, e2 * inv};
#pragma unroll
        for (int s = 0; s < 3; s++) {
            float dl = lr - s_lf0[s];
            float dp = phi - s_th[s];
            float F = __expf(-(dl * dl) * s_i2ls2[s] - (dp * dp) * s_i2t02[s]);
            G = fmaf(F, awv[s], G);
        }
        d_G[i * 4096 + p] = G;
    }
}

// ---------------- kernel 3: survivors only — two-for-one filter + IFFT, overwrite out ------------
__global__ __launch_bounds__(512, 2) void inv_kernel(const float* __restrict__ x,
                                                     const float* __restrict__ fbs,
                                                     const float* __restrict__ mixp,
                                                     float* __restrict__ out) {
    __shared__ float2 sm[FFT_SM_F2];
    __shared__ float2 s_tw[64];
    const int plane = blockIdx.x;
    const int b = plane >> 6, i = plane & 63;
    const int tid = threadIdx.x;
    const int bb = (b + 32) & 63;
    const int si = (int)floorf((fbs[bb * 2 + 0] + 1.f) * 0.5f * 64.f);
    const int ei = (int)floorf((fbs[bb * 2 + 1] + 1.f) * 0.5f * 64.f);
    const int ii = (i + 32) & 63;
    if (!(ii >= si && ii < ei)) return;     // conv-only planes already written by attn
    const int j = ii - si;
    if (j & 1) return;                      // handled by partner block (i-1)
    const bool haspart = (ii + 1 < ei);
    const float mix = mixp[0];
    const float c1 = 1.f - mix;
    const float4* sb4 = ((const float4*)d_sp) + (size_t)b * 1024;

    if (tid < 64) {
        float sn, cs;
        __sincosf(-6.283185307179586f * (float)tid * (1.0f / 64.0f), &sn, &cs);
        s_tw[tid] = make_float2(cs, sn);
    }
    __syncthreads();
    const float* xp0 = x + (size_t)plane * 4096;
    const float* xp1 = xp0 + 4096;
    {
        const int g = tid >> 3, t = tid & 7;
        ull v[8];
#pragma unroll
        for (int n1 = 0; n1 < 8; n1++) {
            int idx = g * 64 + 8 * n1 + t;
            v[n1] = PK(xp0[idx], haspart ? xp1[idx] : 0.f);
        }
        row_pass_reg<-1>(v, sm, s_tw, tid);
    }
    __syncthreads();
    fft_pass<-1, false>(sm, s_tw, tid);
    __syncthreads();
    const float* G0 = d_G + i * 4096;
    const float* G1 = d_G + (i + 1) * 4096;
    float2 P[8];
#pragma unroll
    for (int n = 0; n < 8; n++) {
        int k = tid + n * 512;
        int r = k >> 6, c = k & 63;
        int rm = (64 - r) & 63, cm = (64 - c) & 63;
        int km = rm * 64 + cm;
        float2 Zk = sm[fft_phys(r, c)];
        float2 Zm = sm[fft_phys(rm, cm)];
        int hh = (r + 32) & 63, hhm = (rm + 32) & 63;
        float mr = (hh >= si && hh < ei) ? 0.5f : 0.f;
        float mrm = (hhm >= si && hhm < ei) ? 0.5f : 0.f;
        float g0 = G0[k] * mr + G0[km] * mrm;
        float g1 = haspart ? (G1[k] * mr + G1[km] * mrm) : 0.f;
        float y0x = 0.5f * (Zk.x + Zm.x), y0y = 0.5f * (Zk.y - Zm.y);
        float y1x = 0.5f * (Zk.y + Zm.y), y1y = -0.5f * (Zk.x - Zm.x);
        P[n] = make_float2(y0x * g0 - g1 * y1y, y0y * g0 + g1 * y1x);
    }
    __syncthreads();
#pragma unroll
    for (int n = 0; n < 8; n++) {
        int k = tid + n * 512;
        sm[fft_phys(k >> 6, k & 63)] = P[n];
    }
    __syncthreads();
    fft_pass<1, true>(sm, s_tw, tid);
    __syncthreads();
    fft_pass<1, false>(sm, s_tw, tid);
    __syncthreads();
    const float scale = mix * (1.f / 4096.f);
    float4* op0 = (float4*)(out + (size_t)plane * 4096);
    float4* op1 = (float4*)(out + (size_t)(plane + 1) * 4096);
#pragma unroll
    for (int q = tid; q < 1024; q += 512) {
        int r = q >> 4, c = (q & 15) * 4;
        float2 w0 = sm[fft_phys(r, c + 0)];
        float2 w1v = sm[fft_phys(r, c + 1)];
        float2 w2v = sm[fft_phys(r, c + 2)];
        float2 w3 = sm[fft_phys(r, c + 3)];
        float4 s = sb4[q];
        op0[q] = make_float4(fmaf(scale, w0.x, c1 * s.x), fmaf(scale, w1v.x, c1 * s.y),
                             fmaf(scale, w2v.x, c1 * s.z), fmaf(scale, w3.x, c1 * s.w));
        if (haspart)
            op1[q] = make_float4(fmaf(scale, w0.y, c1 * s.x), fmaf(scale, w1v.y, c1 * s.y),
                                 fmaf(scale, w2v.y, c1 * s.z), fmaf(scale, w3.y, c1 * s.w));
    }
}

// ---------------- launch ----------------
extern "C" void kernel_launch(void* const* d_in, const int* in_sizes, int n_in,
                              void* d_out, int out_size) {
    const float* x      = (const float*)d_in[0];
    const float* f0     = (const float*)d_in[1];
    const float* theta  = (const float*)d_in[2];
    const float* sigma  = (const float*)d_in[3];
    const float* theta0 = (const float*)d_in[4];
    const float* fbs    = (const float*)d_in[5];
    const float* mix    = (const float*)d_in[6];
    const float* w1     = (const float*)d_in[7];
    const float* b1     = (const float*)d_in[8];
    const float* w2     = (const float*)d_in[9];
    const float* b2     = (const float*)d_in[10];
    const float* conv_w = (const float*)d_in[11];
    float* out = (float*)d_out;

    k1_fft_conv<<<3073, 512>>>(x, conv_w, fbs, w1);
    attn_kernel<<<1088, 256>>>(f0, theta, sigma, theta0, b1, w2, b2, fbs, mix, out);
    inv_kernel<<<4096, 512>>>(x, fbs, mix, out);
}